// round 2
// baseline (speedup 1.0000x reference)
#include <cuda_runtime.h>
#include <math.h>

#define BATCH 16
#define DIM 48
#define HID 16
#define CH 8
#define IMH 256
#define IMW 256
#define HXW (IMH*IMW)
#define TW 32
#define TH 16
#define HLW (TW+2)   // 34
#define HLH (TH+2)   // 18
#define NTHREADS 256
#define DCHUNK 12

__device__ __forceinline__ float gelu_exact(float v) {
    return 0.5f * v * (1.0f + erff(v * 0.70710678118654752f));
}

__global__ __launch_bounds__(NTHREADS, 4)
void fused_block_kernel(const float* __restrict__ x,
                        const float* __restrict__ W1,
                        const float* __restrict__ b1,
                        const float* __restrict__ gamma,
                        const float* __restrict__ beta,
                        const float* __restrict__ dww,
                        const float* __restrict__ dwb,
                        const float* __restrict__ pww,
                        const float* __restrict__ pwb,
                        const float* __restrict__ W2,
                        const float* __restrict__ b2,
                        float* __restrict__ out)
{
    __shared__ float sW1[DIM * HID];          // [d][h]
    __shared__ float sW2[CH * DIM];           // [c][d]
    __shared__ float sb1[HID];
    __shared__ float sb2[DIM];
    __shared__ float sg[CH], sbt[CH];
    __shared__ float sdw[CH * 9], sdwb[CH];
    __shared__ float spw[CH * CH], spwb[CH];
    __shared__ float sn[CH][HLH][HLW];        // layernormed x2, halo tile
    __shared__ float sx1[CH][TH][TW];         // gate input x1, interior only

    const int tid = threadIdx.x;

    // ---- load weights to shared ----
    for (int i = tid; i < DIM * HID; i += NTHREADS) sW1[i] = W1[i];
    for (int i = tid; i < CH * DIM;  i += NTHREADS) sW2[i] = W2[i];
    if (tid < HID) sb1[tid] = b1[tid];
    if (tid < DIM) sb2[tid] = b2[tid];
    if (tid < CH) {
        sg[tid]  = gamma[tid];
        sbt[tid] = beta[tid];
        sdwb[tid] = dwb[tid];
        spwb[tid] = pwb[tid];
    }
    for (int i = tid; i < CH * 9;  i += NTHREADS) sdw[i] = dww[i];
    for (int i = tid; i < CH * CH; i += NTHREADS) spw[i] = pww[i];

    const int x0 = blockIdx.x * TW;
    const int y0 = blockIdx.y * TH;
    const int bb = blockIdx.z;
    const float* __restrict__ xin = x + (size_t)bb * (DIM * HXW);

    __syncthreads();

    // ---- Phase 1: GEMM1 + gelu^2 + LN for halo tile ----
    for (int hp = tid; hp < HLH * HLW; hp += NTHREADS) {
        const int hy = hp / HLW;
        const int hx = hp - hy * HLW;
        const int gy = y0 + hy - 1;
        const int gx = x0 + hx - 1;

        if ((unsigned)gy >= IMH || (unsigned)gx >= IMW) {
            // conv 'SAME' zero padding
            #pragma unroll
            for (int c = 0; c < CH; c++) sn[c][hy][hx] = 0.0f;
            continue;
        }

        const bool interior = (hy >= 1) & (hy <= TH) & (hx >= 1) & (hx <= TW);

        const int p = gy * IMW + gx;
        const float4* __restrict__ tv4 = (const float4*)(xin + (size_t)p * DIM);

        float acc[HID];
        #pragma unroll
        for (int h = 0; h < HID; h++) acc[h] = sb1[h];

        #pragma unroll
        for (int dq = 0; dq < DIM / 4; dq++) {
            const float4 tv = tv4[dq];
            const float tvs[4] = {tv.x, tv.y, tv.z, tv.w};
            #pragma unroll
            for (int j = 0; j < 4; j++) {
                const float td = tvs[j];
                const float* wr = &sW1[(dq * 4 + j) * HID];
                #pragma unroll
                for (int h = 0; h < HID; h++) acc[h] += td * wr[h];
            }
        }

        // upper 8 channels: gelu(gelu(.)) + layernorm -> sn
        #pragma unroll
        for (int c = 0; c < CH; c++) {
            float v = gelu_exact(acc[CH + c]);
            acc[CH + c] = gelu_exact(v);
        }

        float m = 0.0f;
        #pragma unroll
        for (int c = 0; c < CH; c++) m += acc[CH + c];
        m *= (1.0f / CH);
        float var = 0.0f;
        #pragma unroll
        for (int c = 0; c < CH; c++) { float d = acc[CH + c] - m; var += d * d; }
        var *= (1.0f / CH);
        const float inv = rsqrtf(var + 1e-5f);

        #pragma unroll
        for (int c = 0; c < CH; c++)
            sn[c][hy][hx] = (acc[CH + c] - m) * inv * sg[c] + sbt[c];

        // lower 8 channels only needed for interior pixels (gate input)
        if (interior) {
            #pragma unroll
            for (int c = 0; c < CH; c++) {
                float v = gelu_exact(acc[c]);
                sx1[c][hy - 1][hx - 1] = gelu_exact(v);
            }
        }
    }

    __syncthreads();

    // ---- Phase 2: dw conv + pw conv + gate + GEMM2 + store ----
    float* __restrict__ outb = out + (size_t)bb * (DIM * HXW);

    for (int it = 0; it < (TH * TW) / NTHREADS; it++) {
        const int p  = tid + it * NTHREADS;
        const int ly = p / TW;
        const int lx = p - ly * TW;
        const int hy = ly + 1;
        const int hx = lx + 1;

        float ncen[CH];
        #pragma unroll
        for (int c = 0; c < CH; c++) ncen[c] = sn[c][hy][hx];

        float g[CH];
        #pragma unroll
        for (int c = 0; c < CH; c++) {
            float sp = sdwb[c];
            #pragma unroll
            for (int ky = 0; ky < 3; ky++) {
                #pragma unroll
                for (int kx = 0; kx < 3; kx++) {
                    sp += sn[c][hy + ky - 1][hx + kx - 1] * sdw[c * 9 + ky * 3 + kx];
                }
            }
            float chv = spwb[c];
            #pragma unroll
            for (int ci = 0; ci < CH; ci++) chv += spw[c * CH + ci] * ncen[ci];
            g[c] = sx1[c][ly][lx] * sp * chv;
        }

        const int gp = (y0 + ly) * IMW + (x0 + lx);

        // GEMM2 chunked over output dim to keep register pressure low
        #pragma unroll
        for (int dc = 0; dc < DIM / DCHUNK; dc++) {
            float oacc[DCHUNK];
            #pragma unroll
            for (int d = 0; d < DCHUNK; d++) oacc[d] = sb2[dc * DCHUNK + d];
            #pragma unroll
            for (int c = 0; c < CH; c++) {
                const float gc = g[c];
                const float* wr = &sW2[c * DIM + dc * DCHUNK];
                #pragma unroll
                for (int d = 0; d < DCHUNK; d++) oacc[d] += gc * wr[d];
            }
            #pragma unroll
            for (int d = 0; d < DCHUNK; d++)
                outb[(size_t)(dc * DCHUNK + d) * HXW + gp] = oacc[d];
        }
    }
}

extern "C" void kernel_launch(void* const* d_in, const int* in_sizes, int n_in,
                              void* d_out, int out_size)
{
    const float* x     = (const float*)d_in[0];
    const float* W1    = (const float*)d_in[1];
    const float* b1    = (const float*)d_in[2];
    const float* gamma = (const float*)d_in[3];
    const float* beta  = (const float*)d_in[4];
    const float* dww   = (const float*)d_in[5];
    const float* dwb   = (const float*)d_in[6];
    const float* pww   = (const float*)d_in[7];
    const float* pwb   = (const float*)d_in[8];
    const float* W2    = (const float*)d_in[9];
    const float* b2    = (const float*)d_in[10];
    float* out = (float*)d_out;

    dim3 grid(IMW / TW, IMH / TH, BATCH);   // 8 x 16 x 16
    fused_block_kernel<<<grid, NTHREADS>>>(x, W1, b1, gamma, beta,
                                           dww, dwb, pww, pwb, W2, b2, out);
}

// round 3
// speedup vs baseline: 3.1366x; 3.1366x over previous
#include <cuda_runtime.h>
#include <math.h>

#define BATCH 16
#define DIM 48
#define HID 16
#define CH 8
#define IMH 256
#define IMW 256
#define HXW (IMH*IMW)
#define NPIX (BATCH*HXW)          // 1,048,576
#define PADW (IMW+2)              // 258
#define PADH (IMH+2)              // 258
#define PPLANE (PADH*PADW)        // 66564 per (ch,b) plane
#define NTHREADS 256

// scratch: LN'd x2 in zero-padded planes [ch][b][258][258]  (ring stays 0 => free 'SAME' pad)
__device__ float g_n[CH * BATCH * PPLANE];     // ~34 MB
// gate input x1 planar [ch][b][65536]
__device__ float g_x1[CH * BATCH * HXW];       // ~33.5 MB

__device__ __forceinline__ float gelu_exact(float v) {
    return 0.5f * v * (1.0f + erff(v * 0.70710678118654752f));
}

// ---------------- Kernel A: GEMM1 + gelu^2 + LN ----------------
__global__ __launch_bounds__(NTHREADS)
void stage_a_kernel(const float* __restrict__ x,
                    const float* __restrict__ W1,
                    const float* __restrict__ b1,
                    const float* __restrict__ gamma,
                    const float* __restrict__ beta)
{
    __shared__ float sW1[DIM * HID];
    __shared__ float sb1[HID];
    __shared__ float sg[CH], sbt[CH];

    const int tid = threadIdx.x;
    for (int i = tid; i < DIM * HID; i += NTHREADS) sW1[i] = W1[i];
    if (tid < HID) sb1[tid] = b1[tid];
    if (tid < CH) { sg[tid] = gamma[tid]; sbt[tid] = beta[tid]; }
    __syncthreads();

    const int p = blockIdx.x * NTHREADS + tid;      // global pixel 0..NPIX-1
    const int b   = p >> 16;                        // p / HXW
    const int pos = p & (HXW - 1);
    const int h = pos >> 8;
    const int w = pos & 255;

    const float4* __restrict__ tv4 = (const float4*)(x + (size_t)p * DIM);

    float acc[HID];
    #pragma unroll
    for (int hh = 0; hh < HID; hh++) acc[hh] = sb1[hh];

    #pragma unroll
    for (int dq = 0; dq < DIM / 4; dq++) {
        const float4 tv = tv4[dq];
        const float tvs[4] = {tv.x, tv.y, tv.z, tv.w};
        #pragma unroll
        for (int j = 0; j < 4; j++) {
            const float td = tvs[j];
            const float* wr = &sW1[(dq * 4 + j) * HID];
            #pragma unroll
            for (int hh = 0; hh < HID; hh++) acc[hh] += td * wr[hh];
        }
    }

    #pragma unroll
    for (int hh = 0; hh < HID; hh++)
        acc[hh] = gelu_exact(gelu_exact(acc[hh]));

    // layernorm over channels 8..15
    float m = 0.0f;
    #pragma unroll
    for (int c = 0; c < CH; c++) m += acc[CH + c];
    m *= (1.0f / CH);
    float var = 0.0f;
    #pragma unroll
    for (int c = 0; c < CH; c++) { float d = acc[CH + c] - m; var += d * d; }
    var *= (1.0f / CH);
    const float inv = rsqrtf(var + 1e-5f);

    const int padidx = b * PPLANE + (h + 1) * PADW + (w + 1);
    #pragma unroll
    for (int c = 0; c < CH; c++)
        g_n[(size_t)c * (BATCH * PPLANE) + padidx] =
            (acc[CH + c] - m) * inv * sg[c] + sbt[c];

    #pragma unroll
    for (int c = 0; c < CH; c++)
        g_x1[(size_t)c * NPIX + p] = acc[c];
}

// ---------------- Kernel B: conv + gate + GEMM2 ----------------
__global__ __launch_bounds__(NTHREADS)
void stage_b_kernel(const float* __restrict__ dww,
                    const float* __restrict__ dwb,
                    const float* __restrict__ pww,
                    const float* __restrict__ pwb,
                    const float* __restrict__ W2,
                    const float* __restrict__ b2,
                    float* __restrict__ out)
{
    __shared__ float sW2[CH * DIM];
    __shared__ float sb2[DIM];
    __shared__ float sdw[CH * 9], sdwb[CH];
    __shared__ float spw[CH * CH], spwb[CH];

    const int tid = threadIdx.x;
    for (int i = tid; i < CH * DIM; i += NTHREADS) sW2[i] = W2[i];
    if (tid < DIM) sb2[tid] = b2[tid];
    if (tid < CH) { sdwb[tid] = dwb[tid]; spwb[tid] = pwb[tid]; }
    for (int i = tid; i < CH * 9;  i += NTHREADS) sdw[i] = dww[i];
    for (int i = tid; i < CH * CH; i += NTHREADS) spw[i] = pww[i];
    __syncthreads();

    const int p = blockIdx.x * NTHREADS + tid;
    const int b   = p >> 16;
    const int pos = p & (HXW - 1);
    const int h = pos >> 8;
    const int w = pos & 255;

    // center index in padded plane
    const int pc = b * PPLANE + (h + 1) * PADW + (w + 1);

    float g[CH];
    #pragma unroll
    for (int c = 0; c < CH; c++) {
        const float* __restrict__ np = &g_n[(size_t)c * (BATCH * PPLANE) + pc];
        const float n00 = np[-PADW - 1], n01 = np[-PADW], n02 = np[-PADW + 1];
        const float n10 = np[-1],        n11 = np[0],     n12 = np[1];
        const float n20 = np[PADW - 1],  n21 = np[PADW],  n22 = np[PADW + 1];

        const float* kw = &sdw[c * 9];
        float sp = sdwb[c];
        sp += n00 * kw[0]; sp += n01 * kw[1]; sp += n02 * kw[2];
        sp += n10 * kw[3]; sp += n11 * kw[4]; sp += n12 * kw[5];
        sp += n20 * kw[6]; sp += n21 * kw[7]; sp += n22 * kw[8];
        g[c] = sp;   // temporarily hold spatial branch
    }

    // pointwise conv needs all 8 center values: reload centers (L1-hot)
    float ncen[CH];
    #pragma unroll
    for (int c = 0; c < CH; c++)
        ncen[c] = g_n[(size_t)c * (BATCH * PPLANE) + pc];

    #pragma unroll
    for (int c = 0; c < CH; c++) {
        float chv = spwb[c];
        #pragma unroll
        for (int ci = 0; ci < CH; ci++) chv += spw[c * CH + ci] * ncen[ci];
        const float x1v = g_x1[(size_t)c * NPIX + p];
        g[c] = x1v * g[c] * chv;
    }

    float* __restrict__ outb = out + (size_t)b * (DIM * HXW) + pos;

    #pragma unroll
    for (int dc = 0; dc < 3; dc++) {
        float oacc[16];
        #pragma unroll
        for (int d = 0; d < 16; d++) oacc[d] = sb2[dc * 16 + d];
        #pragma unroll
        for (int c = 0; c < CH; c++) {
            const float gc = g[c];
            const float* wr = &sW2[c * DIM + dc * 16];
            #pragma unroll
            for (int d = 0; d < 16; d++) oacc[d] += gc * wr[d];
        }
        #pragma unroll
        for (int d = 0; d < 16; d++)
            outb[(size_t)(dc * 16 + d) * HXW] = oacc[d];
    }
}

extern "C" void kernel_launch(void* const* d_in, const int* in_sizes, int n_in,
                              void* d_out, int out_size)
{
    const float* x     = (const float*)d_in[0];
    const float* W1    = (const float*)d_in[1];
    const float* b1    = (const float*)d_in[2];
    const float* gamma = (const float*)d_in[3];
    const float* beta  = (const float*)d_in[4];
    const float* dww   = (const float*)d_in[5];
    const float* dwb   = (const float*)d_in[6];
    const float* pww   = (const float*)d_in[7];
    const float* pwb   = (const float*)d_in[8];
    const float* W2    = (const float*)d_in[9];
    const float* b2    = (const float*)d_in[10];
    float* out = (float*)d_out;

    const int nblk = NPIX / NTHREADS;   // 4096
    stage_a_kernel<<<nblk, NTHREADS>>>(x, W1, b1, gamma, beta);
    stage_b_kernel<<<nblk, NTHREADS>>>(dww, dwb, pww, pwb, W2, b2, out);
}

// round 5
// speedup vs baseline: 4.6104x; 1.4699x over previous
#include <cuda_runtime.h>
#include <math.h>

#define BATCH 16
#define DIM 48
#define HID 16
#define CH 8
#define IMH 256
#define IMW 256
#define HXW (IMH*IMW)
#define NPIX (BATCH*HXW)          // 1,048,576
#define PADW 264                  // padded plane row stride (mult of 8 for float4 alignment)
#define PADH 258
#define PPLANE (PADH*PADW)        // 68112 (mult of 4)
#define NTHREADS 256

// scratch: LN'd x2 in zero-padded planes [ch][b][258][264] (ring stays 0 => free 'SAME' pad)
__device__ __align__(16) float g_n[CH * BATCH * PPLANE];
// gate input x1 planar [ch][b][65536]
__device__ __align__(16) float g_x1[CH * BATCH * HXW];

typedef unsigned long long ull;

__device__ __forceinline__ ull bcast2(float a) {
    ull r; asm("mov.b64 %0, {%1, %1};" : "=l"(r) : "f"(a)); return r;
}
__device__ __forceinline__ void fma2(ull &d, ull a, ull b) {
    asm("fma.rn.f32x2 %0, %1, %2, %0;" : "+l"(d) : "l"(a), "l"(b));
}
__device__ __forceinline__ void unpack2(ull v, float &a, float &b) {
    asm("mov.b64 {%0, %1}, %2;" : "=f"(a), "=f"(b) : "l"(v));
}

__device__ __forceinline__ float gelu_exact(float v) {
    return 0.5f * v * (1.0f + erff(v * 0.70710678118654752f));
}

// ---------------- Kernel A: GEMM1 (packed f32x2) + gelu^2 + LN, 2 px/thread ----------------
__global__ __launch_bounds__(NTHREADS)
void stage_a_kernel(const float* __restrict__ x,
                    const float* __restrict__ W1,
                    const float* __restrict__ b1,
                    const float* __restrict__ gamma,
                    const float* __restrict__ beta)
{
    __shared__ __align__(16) float sW1[DIM * HID];
    __shared__ __align__(16) float sb1[HID];
    __shared__ float sg[CH], sbt[CH];

    const int tid = threadIdx.x;
    for (int i = tid; i < DIM * HID; i += NTHREADS) sW1[i] = W1[i];
    if (tid < HID) sb1[tid] = b1[tid];
    if (tid < CH) { sg[tid] = gamma[tid]; sbt[tid] = beta[tid]; }
    __syncthreads();

    const int t  = blockIdx.x * NTHREADS + tid;
    const int p0 = t * 2;                      // two consecutive pixels, same row
    const int b   = p0 >> 16;
    const int pos = p0 & (HXW - 1);
    const int h = pos >> 8;
    const int w = pos & 255;

    const float4* __restrict__ tv0 = (const float4*)(x + (size_t)p0 * DIM);
    const float4* __restrict__ tv1 = (const float4*)(x + (size_t)(p0 + 1) * DIM);

    ull acc0[CH], acc1[CH];
    {
        const ull* sb1p = (const ull*)sb1;
        #pragma unroll
        for (int i = 0; i < CH; i++) { ull v = sb1p[i]; acc0[i] = v; acc1[i] = v; }
    }

    #pragma unroll
    for (int dq = 0; dq < DIM / 4; dq++) {
        const float4 a4 = tv0[dq];
        const float4 c4 = tv1[dq];
        const float av[4] = {a4.x, a4.y, a4.z, a4.w};
        const float cv[4] = {c4.x, c4.y, c4.z, c4.w};
        #pragma unroll
        for (int j = 0; j < 4; j++) {
            const ull ta = bcast2(av[j]);
            const ull tb = bcast2(cv[j]);
            const ull* wr = (const ull*)&sW1[(dq * 4 + j) * HID];
            #pragma unroll
            for (int i = 0; i < CH; i++) {
                const ull wv = wr[i];
                fma2(acc0[i], ta, wv);
                fma2(acc1[i], tb, wv);
            }
        }
    }

    #pragma unroll
    for (int px = 0; px < 2; px++) {
        float acc[HID];
        #pragma unroll
        for (int i = 0; i < CH; i++)
            unpack2(px == 0 ? acc0[i] : acc1[i], acc[2 * i], acc[2 * i + 1]);

        #pragma unroll
        for (int hh = 0; hh < HID; hh++)
            acc[hh] = gelu_exact(gelu_exact(acc[hh]));

        float m = 0.0f;
        #pragma unroll
        for (int c = 0; c < CH; c++) m += acc[CH + c];
        m *= (1.0f / CH);
        float var = 0.0f;
        #pragma unroll
        for (int c = 0; c < CH; c++) { float d = acc[CH + c] - m; var += d * d; }
        var *= (1.0f / CH);
        const float inv = rsqrtf(var + 1e-5f);

        const int padidx = b * PPLANE + (h + 1) * PADW + (w + px + 1);
        #pragma unroll
        for (int c = 0; c < CH; c++)
            g_n[(size_t)c * (BATCH * PPLANE) + padidx] =
                (acc[CH + c] - m) * inv * sg[c] + sbt[c];

        #pragma unroll
        for (int c = 0; c < CH; c++)
            g_x1[(size_t)c * NPIX + p0 + px] = acc[c];
    }
}

// ---------------- Kernel B: conv + gate + GEMM2, 4 px/thread, vector loads ----------------
__global__ __launch_bounds__(NTHREADS, 2)
void stage_b_kernel(const float* __restrict__ dww,
                    const float* __restrict__ dwb,
                    const float* __restrict__ pww,
                    const float* __restrict__ pwb,
                    const float* __restrict__ W2,
                    const float* __restrict__ b2,
                    float* __restrict__ out)
{
    __shared__ float sW2[CH * DIM];
    __shared__ float sb2[DIM];
    __shared__ float sdw[CH * 9], sdwb[CH];
    __shared__ float spw[CH * CH], spwb[CH];

    const int tid = threadIdx.x;
    for (int i = tid; i < CH * DIM; i += NTHREADS) sW2[i] = W2[i];
    if (tid < DIM) sb2[tid] = b2[tid];
    if (tid < CH) { sdwb[tid] = dwb[tid]; spwb[tid] = pwb[tid]; }
    for (int i = tid; i < CH * 9;  i += NTHREADS) sdw[i] = dww[i];
    for (int i = tid; i < CH * CH; i += NTHREADS) spw[i] = pww[i];
    __syncthreads();

    const int t  = blockIdx.x * NTHREADS + tid;
    const int p0 = t * 4;                       // 4 consecutive pixels, same row
    const int b   = p0 >> 16;
    const int pos = p0 & (HXW - 1);
    const int h  = pos >> 8;
    const int w0 = pos & 255;                   // multiple of 4

    // top-left of 3x6 neighborhood in padded plane:
    // center of pixel (h,w) is at padded (h+1, w+1); we need rows h..h+2, cols w0..w0+5
    const int rb = b * PPLANE + h * PADW + w0;

    float sp[CH][4];     // depthwise results
    float nc[CH][4];     // center values (for pointwise)

    #pragma unroll
    for (int c = 0; c < CH; c++) {
        const float* __restrict__ np = &g_n[(size_t)c * (BATCH * PPLANE) + rb];

        const float4 r0a = *(const float4*)np;
        const float2 r0b = *(const float2*)(np + 4);
        const float4 r1a = *(const float4*)(np + PADW);
        const float2 r1b = *(const float2*)(np + PADW + 4);
        const float4 r2a = *(const float4*)(np + 2 * PADW);
        const float2 r2b = *(const float2*)(np + 2 * PADW + 4);

        const float v0[6] = {r0a.x, r0a.y, r0a.z, r0a.w, r0b.x, r0b.y};
        const float v1[6] = {r1a.x, r1a.y, r1a.z, r1a.w, r1b.x, r1b.y};
        const float v2[6] = {r2a.x, r2a.y, r2a.z, r2a.w, r2b.x, r2b.y};

        const float* kw = &sdw[c * 9];
        #pragma unroll
        for (int i = 0; i < 4; i++) {
            float s = sdwb[c];
            s += v0[i] * kw[0]; s += v0[i + 1] * kw[1]; s += v0[i + 2] * kw[2];
            s += v1[i] * kw[3]; s += v1[i + 1] * kw[4]; s += v1[i + 2] * kw[5];
            s += v2[i] * kw[6]; s += v2[i + 1] * kw[7]; s += v2[i + 2] * kw[8];
            sp[c][i] = s;
            nc[c][i] = v1[i + 1];
        }
    }

    // pointwise conv + gate
    float g[CH][4];
    #pragma unroll
    for (int c = 0; c < CH; c++) {
        float ch0 = spwb[c], ch1 = spwb[c], ch2 = spwb[c], ch3 = spwb[c];
        #pragma unroll
        for (int ci = 0; ci < CH; ci++) {
            const float wv = spw[c * CH + ci];
            ch0 += wv * nc[ci][0];
            ch1 += wv * nc[ci][1];
            ch2 += wv * nc[ci][2];
            ch3 += wv * nc[ci][3];
        }
        const float4 x1v = *(const float4*)&g_x1[(size_t)c * NPIX + p0];
        g[c][0] = x1v.x * sp[c][0] * ch0;
        g[c][1] = x1v.y * sp[c][1] * ch1;
        g[c][2] = x1v.z * sp[c][2] * ch2;
        g[c][3] = x1v.w * sp[c][3] * ch3;
    }

    float* __restrict__ outb = out + (size_t)b * (DIM * HXW) + pos;

    // GEMM2: 4 output channels x 4 pixels per chunk
    #pragma unroll
    for (int dc = 0; dc < DIM / 4; dc++) {
        float o[4][4];
        #pragma unroll
        for (int j = 0; j < 4; j++) {
            const float bv = sb2[dc * 4 + j];
            o[j][0] = bv; o[j][1] = bv; o[j][2] = bv; o[j][3] = bv;
        }
        #pragma unroll
        for (int c = 0; c < CH; c++) {
            #pragma unroll
            for (int j = 0; j < 4; j++) {
                const float wv = sW2[c * DIM + dc * 4 + j];
                o[j][0] += g[c][0] * wv;
                o[j][1] += g[c][1] * wv;
                o[j][2] += g[c][2] * wv;
                o[j][3] += g[c][3] * wv;
            }
        }
        #pragma unroll
        for (int j = 0; j < 4; j++) {
            float4 ov = {o[j][0], o[j][1], o[j][2], o[j][3]};
            *(float4*)(outb + (size_t)(dc * 4 + j) * HXW) = ov;
        }
    }
}

extern "C" void kernel_launch(void* const* d_in, const int* in_sizes, int n_in,
                              void* d_out, int out_size)
{
    const float* x     = (const float*)d_in[0];
    const float* W1    = (const float*)d_in[1];
    const float* b1    = (const float*)d_in[2];
    const float* gamma = (const float*)d_in[3];
    const float* beta  = (const float*)d_in[4];
    const float* dww   = (const float*)d_in[5];
    const float* dwb   = (const float*)d_in[6];
    const float* pww   = (const float*)d_in[7];
    const float* pwb   = (const float*)d_in[8];
    const float* W2    = (const float*)d_in[9];
    const float* b2    = (const float*)d_in[10];
    float* out = (float*)d_out;

    stage_a_kernel<<<NPIX / 2 / NTHREADS, NTHREADS>>>(x, W1, b1, gamma, beta);
    stage_b_kernel<<<NPIX / 4 / NTHREADS, NTHREADS>>>(dww, dwb, pww, pwb, W2, b2, out);
}